// round 7
// baseline (speedup 1.0000x reference)
#include <cuda_runtime.h>
#include <math.h>

#define HH 1024
#define WW 1024
#define NPIX (HH * WW)
#define R_STRIP 8
#define BLK_B 256
#define PPT 4                              // pixels per thread in kernel B
#define TOTAL_B ((NPIX / PPT / BLK_B) * 2) // ticket count for finalize

__device__ unsigned char g_edge[2][NPIX];  // edge flags (0/1)
__device__ float         g_g2[2][NPIX];    // row 1D distance SQUARED (f32, sentinel baked)
__device__ float         g_sums[2];
__device__ unsigned int  g_count;

// ---------------------------------------------------------------------------
// Kernel A: fused edges + row EDT, word-parallel.
// 1024-thread block per (8-row strip, image). Thread (c = tid&255, s = tid>>8)
// owns pixels 4c..4c+3 of rows {2s, 2s+1} in the strip.
//  - float4 loads -> 0/1 flag bytes in shared (strip + halo, loaded once)
//  - erosion on 4 pixels at once with bytewise AND on u32 words
//  - per-row outward scan to nearest edge; writes g^2 as f32 with the
//    featureless-row sentinel (1e6 - j)^2 baked in (identical f32 rounding
//    to the reference's g*g).
// Also zeroes accumulators/ticket each graph replay.
// ---------------------------------------------------------------------------
__global__ void __launch_bounds__(1024) edges_row_kernel(
        const float* __restrict__ preds, const float* __restrict__ targets) {
    __shared__ unsigned char sflag[R_STRIP + 2][WW];
    __shared__ unsigned char sfeat[R_STRIP][WW];
    int img   = blockIdx.y;
    int strip = blockIdx.x;
    int tid   = threadIdx.x;
    int c     = tid & 255;        // word index (4 pixels)
    int s     = tid >> 8;         // 0..3 row slot
    int y0    = strip * R_STRIP;
    if (img == 0 && strip == 0 && tid < 3) {
        if (tid < 2) g_sums[tid] = 0.0f; else g_count = 0u;
    }
    const float* __restrict__ seg = (img == 0) ? preds : targets;
    // load flags: rows rr = s, s+4, s+8 (halo rows rr-1 in [-1, R_STRIP])
    #pragma unroll
    for (int rr = s; rr < R_STRIP + 2; rr += 4) {
        int y = y0 + rr - 1;
        unsigned int fw = 0;
        if (y >= 0 && y < HH) {
            float4 v = *(const float4*)&seg[y * WW + 4 * c];
            fw = (v.x == 1.0f ? 0x01u : 0u) | (v.y == 1.0f ? 0x0100u : 0u)
               | (v.z == 1.0f ? 0x010000u : 0u) | (v.w == 1.0f ? 0x01000000u : 0u);
        }
        *(unsigned int*)&sflag[rr][4 * c] = fw;
    }
    __syncthreads();
    // erosion, rows rloc = 2s and 2s+1
    #pragma unroll
    for (int q = 0; q < 2; q++) {
        int rloc = 2 * s + q;
        int rs   = rloc + 1;
        int y    = y0 + rloc;
        const unsigned int* r0 = (const unsigned int*)sflag[rs - 1];
        const unsigned int* r1 = (const unsigned int*)sflag[rs];
        const unsigned int* r2 = (const unsigned int*)sflag[rs + 1];
        unsigned int er = 0;
        unsigned int mid = r1[c];
        if (y > 0 && y < HH - 1) {
            unsigned int h[3];
            #pragma unroll
            for (int k = 0; k < 3; k++) {
                const unsigned int* rw = (k == 0) ? r0 : (k == 1) ? r1 : r2;
                unsigned int w = rw[c];
                unsigned int wl = (c > 0)   ? rw[c - 1] : 0u;
                unsigned int wr = (c < 255) ? rw[c + 1] : 0u;
                unsigned int left  = (w << 8) | (wl >> 24);  // byte at j-1
                unsigned int right = (w >> 8) | (wr << 24);  // byte at j+1
                h[k] = w & left & right;
            }
            er = h[0] & h[1] & h[2];
            if (c == 0)   er &= 0xFFFFFF00u;   // j = 0 not interior
            if (c == 255) er &= 0x00FFFFFFu;   // j = 1023 not interior
        }
        unsigned int f4 = mid & ~er & 0x01010101u;
        *(unsigned int*)&sfeat[rloc][4 * c]          = f4;
        *(unsigned int*)&g_edge[img][y * WW + 4 * c] = f4;
    }
    __syncthreads();
    // row scan, same rows, 4 pixels each
    #pragma unroll
    for (int q = 0; q < 2; q++) {
        int rloc = 2 * s + q;
        int y    = y0 + rloc;
        const unsigned char* __restrict__ ft = sfeat[rloc];
        float o[4];
        #pragma unroll
        for (int p = 0; p < 4; p++) {
            int jj = 4 * c + p;
            float g2;
            if (ft[jj]) {
                g2 = 0.0f;
            } else {
                int r = 1;
                for (; r < WW; r++) {
                    int jl = jj - r, jr = jj + r;
                    if ((jl >= 0 && ft[jl]) || (jr < WW && ft[jr])) break;
                }
                float gf = (r < WW) ? (float)r : (1e6f - (float)jj);
                g2 = gf * gf;
            }
            o[p] = g2;
        }
        *(float4*)&g_g2[img][y * WW + 4 * c] = make_float4(o[0], o[1], o[2], o[3]);
    }
}

// ---------------------------------------------------------------------------
// Kernel B: column lower-envelope min, 4 horizontal pixels per thread.
// g2 pre-squared f32 -> inner loop is just FADD + FMIN per pixel per side.
// Group early-exit on max(best) is lossless (g2 + rr >= rr >= need).
// Fused block reduction + ticket finalize -> sigmoid scalar.
// ---------------------------------------------------------------------------
__global__ void __launch_bounds__(BLK_B) col_reduce_finalize_kernel(float* __restrict__ out) {
    int img = blockIdx.y;
    int t = blockIdx.x * blockDim.x + threadIdx.x;   // 0 .. NPIX/4-1
    int idx4 = t * PPT;
    int i = idx4 >> 10;
    float val = 0.0f;
    uchar4 w4 = *(const uchar4*)&g_edge[1 - img][idx4];
    if (w4.x | w4.y | w4.z | w4.w) {
        const float* __restrict__ gg = g_g2[img];
        unsigned char wa[4] = {w4.x, w4.y, w4.z, w4.w};
        float4 g0 = *(const float4*)&gg[idx4];
        float best[4];
        best[0] = wa[0] ? g0.x : 0.0f;
        best[1] = wa[1] ? g0.y : 0.0f;
        best[2] = wa[2] ? g0.z : 0.0f;
        best[3] = wa[3] ? g0.w : 0.0f;
        float need = fmaxf(fmaxf(best[0], best[1]), fmaxf(best[2], best[3]));
        for (int r = 1; r < HH; r++) {
            float rr = (float)(r * r);
            if (rr >= need) break;
            int ku = i - r, kd = i + r;
            if (ku >= 0) {
                float4 u = *(const float4*)&gg[(idx4 - (r << 10))];
                best[0] = fminf(best[0], u.x + rr);
                best[1] = fminf(best[1], u.y + rr);
                best[2] = fminf(best[2], u.z + rr);
                best[3] = fminf(best[3], u.w + rr);
            }
            if (kd < HH) {
                float4 u = *(const float4*)&gg[(idx4 + (r << 10))];
                best[0] = fminf(best[0], u.x + rr);
                best[1] = fminf(best[1], u.y + rr);
                best[2] = fminf(best[2], u.z + rr);
                best[3] = fminf(best[3], u.w + rr);
            }
            need = fmaxf(fmaxf(best[0], best[1]), fmaxf(best[2], best[3]));
        }
        #pragma unroll
        for (int cpx = 0; cpx < 4; cpx++)
            if (wa[cpx]) val += sqrtf(best[cpx]);
    }
    // block reduction
    __shared__ float warpsum[BLK_B / 32];
    #pragma unroll
    for (int off = 16; off > 0; off >>= 1)
        val += __shfl_down_sync(0xffffffffu, val, off);
    int lane = threadIdx.x & 31;
    int wid  = threadIdx.x >> 5;
    if (lane == 0) warpsum[wid] = val;
    __syncthreads();
    if (wid == 0) {
        val = (lane < (BLK_B >> 5)) ? warpsum[lane] : 0.0f;
        #pragma unroll
        for (int off = 4; off > 0; off >>= 1)
            val += __shfl_down_sync(0xffffffffu, val, off);
        if (lane == 0) {
            atomicAdd(&g_sums[img], val);
            __threadfence();
            unsigned int tkt = atomicAdd(&g_count, 1u);
            if (tkt == (unsigned int)(TOTAL_B - 1)) {
                float s0 = atomicAdd(&g_sums[0], 0.0f);
                float s1 = atomicAdd(&g_sums[1], 0.0f);
                float invN = 1.0f / (float)NPIX;
                float loss = (s0 * invN + s1 * invN) * 0.5f;
                out[0] = 1.0f / (1.0f + expf(-loss));
            }
        }
    }
}

extern "C" void kernel_launch(void* const* d_in, const int* in_sizes, int n_in,
                              void* d_out, int out_size) {
    const float* preds   = (const float*)d_in[0];
    const float* targets = (const float*)d_in[1];
    float* out = (float*)d_out;

    edges_row_kernel<<<dim3(HH / R_STRIP, 2), dim3(1024)>>>(preds, targets);
    col_reduce_finalize_kernel<<<dim3(NPIX / PPT / BLK_B, 2), dim3(BLK_B)>>>(out);
}

// round 8
// speedup vs baseline: 1.2533x; 1.2533x over previous
#include <cuda_runtime.h>
#include <math.h>

#define HH 1024
#define WW 1024
#define NPIX (HH * WW)
#define NBLK 148
#define NTHR 1024
#define PPT 4
#define HALF (NPIX / PPT)          // thread-tasks per image in phase 2
#define T2 (2 * HALF)

__device__ unsigned char  g_edge[2][NPIX];  // edge flags (0/1)
__device__ unsigned short g_g[2][NPIX];     // row 1D distance (0xFFFF = featureless row)
__device__ float          g_sums[2];
__device__ unsigned int   g_count;          // finalize ticket
__device__ unsigned int   g_bar;            // global phase barrier

__device__ __forceinline__ unsigned int hand3(unsigned int w, unsigned int wl, unsigned int wr) {
    // bit b: w[b] & w[b-1] & w[b+1], with cross-word carries
    return w & ((w << 1) | (wl >> 31)) & ((w >> 1) | (wr << 31));
}

__global__ void __launch_bounds__(NTHR, 1) boundary_loss_kernel(
        const float* __restrict__ preds, const float* __restrict__ targets,
        float* __restrict__ out) {
    __shared__ unsigned int su[32], sc[32], sd[32], sfeat[32];
    __shared__ float warpsum0[NTHR / 32], warpsum1[NTHR / 32];
    int tid = threadIdx.x;
    int wi = tid >> 5, bi = tid & 31;

    // ---------------- Phase 1: edges + row EDT (bitmask) ----------------
    for (int task = blockIdx.x; task < 2 * HH; task += NBLK) {
        int img = task >> 10;
        int y   = task & (HH - 1);
        const float* __restrict__ seg = img ? targets : preds;
        bool fc = (seg[y * WW + tid] == 1.0f);
        bool fu = (y > 0)      ? (seg[(y - 1) * WW + tid] == 1.0f) : false;
        bool fd = (y < HH - 1) ? (seg[(y + 1) * WW + tid] == 1.0f) : false;
        unsigned int bu = __ballot_sync(0xffffffffu, fu);
        unsigned int bc = __ballot_sync(0xffffffffu, fc);
        unsigned int bd = __ballot_sync(0xffffffffu, fd);
        if (bi == 0) { su[wi] = bu; sc[wi] = bc; sd[wi] = bd; }
        __syncthreads();
        if (tid < 32) {
            int w = tid;
            unsigned int er = 0;
            if (y > 0 && y < HH - 1) {
                unsigned int ul = w ? su[w-1] : 0u, ur = (w < 31) ? su[w+1] : 0u;
                unsigned int cl = w ? sc[w-1] : 0u, cr = (w < 31) ? sc[w+1] : 0u;
                unsigned int dl = w ? sd[w-1] : 0u, dr = (w < 31) ? sd[w+1] : 0u;
                er = hand3(su[w], ul, ur) & hand3(sc[w], cl, cr) & hand3(sd[w], dl, dr);
                if (w == 0)  er &= ~1u;           // j = 0 not interior
                if (w == 31) er &= 0x7FFFFFFFu;   // j = 1023 not interior
            }
            sfeat[w] = sc[w] & ~er;
        }
        __syncthreads();
        unsigned int self = sfeat[wi];
        unsigned int mybit = (self >> bi) & 1u;
        g_edge[img][y * WW + tid] = (unsigned char)mybit;
        unsigned short gv;
        if (mybit) {
            gv = 0;
        } else {
            int ld = 1 << 20, rd = 1 << 20;
            unsigned int ml = (bi == 0) ? 0u : (self & (0xFFFFFFFFu >> (32 - bi)));
            if (ml) ld = bi - (31 - __clz(ml));
            else {
                for (int k = wi - 1; k >= 0; k--) {
                    unsigned int w2 = sfeat[k];
                    if (w2) { ld = (wi - k) * 32 + bi - (31 - __clz(w2)); break; }
                }
            }
            unsigned int mr = (bi == 31) ? 0u : (self & (0xFFFFFFFEu << bi));
            if (mr) rd = (__ffs(mr) - 1) - bi;
            else {
                for (int k = wi + 1; k < 32; k++) {
                    unsigned int w2 = sfeat[k];
                    if (w2) { rd = (k - wi) * 32 + (__ffs(w2) - 1) - bi; break; }
                }
            }
            int d = min(ld, rd);
            gv = (d >= (1 << 20)) ? (unsigned short)0xFFFF : (unsigned short)d;
        }
        g_g[img][y * WW + tid] = gv;
        // next iteration's __syncthreads (after ballot stores) protects sfeat reuse
    }

    // ---------------- Global barrier (all 148 blocks resident) ----------------
    __syncthreads();
    __threadfence();
    if (tid == 0) {
        atomicAdd(&g_bar, 1u);
        while (atomicAdd(&g_bar, 0u) < (unsigned int)NBLK) __nanosleep(64);
    }
    __syncthreads();
    __threadfence();

    // ---------------- Phase 2: column envelope + weighted reduce ----------------
    float val0 = 0.0f, val1 = 0.0f;
    int gtid = blockIdx.x * NTHR + tid;
    for (int t = gtid; t < T2; t += NBLK * NTHR) {
        int img = (t >= HALF);
        int tl  = img ? (t - HALF) : t;
        int idx4 = tl * PPT;
        int i  = idx4 >> 10;
        int j0 = idx4 & (WW - 1);
        uchar4 w4 = *(const uchar4*)&g_edge[1 - img][idx4];
        if (!(w4.x | w4.y | w4.z | w4.w)) continue;
        const unsigned short* __restrict__ gg = g_g[img];
        unsigned char wa[4] = {w4.x, w4.y, w4.z, w4.w};
        ushort4 gv4 = *(const ushort4*)&gg[idx4];
        unsigned short ga[4] = {gv4.x, gv4.y, gv4.z, gv4.w};
        float best[4];
        float need = 0.0f;
        #pragma unroll
        for (int c = 0; c < 4; c++) {
            float gf = (ga[c] == 0xFFFFu) ? (1e6f - (float)(j0 + c)) : (float)ga[c];
            best[c] = wa[c] ? gf * gf : 0.0f;
            need = fmaxf(need, best[c]);
        }
        for (int r = 1; r < HH; r++) {
            float rr = (float)(r * r);
            if (rr >= need) break;
            int ku = i - r, kd = i + r;
            if (ku >= 0) {
                ushort4 u4 = *(const ushort4*)&gg[ku * WW + j0];
                unsigned short ua[4] = {u4.x, u4.y, u4.z, u4.w};
                #pragma unroll
                for (int c = 0; c < 4; c++) {
                    float f2 = (ua[c] == 0xFFFFu) ? (1e6f - (float)(j0 + c)) : (float)ua[c];
                    best[c] = fminf(best[c], f2 * f2 + rr);
                }
            }
            if (kd < HH) {
                ushort4 u4 = *(const ushort4*)&gg[kd * WW + j0];
                unsigned short ua[4] = {u4.x, u4.y, u4.z, u4.w};
                #pragma unroll
                for (int c = 0; c < 4; c++) {
                    float f2 = (ua[c] == 0xFFFFu) ? (1e6f - (float)(j0 + c)) : (float)ua[c];
                    best[c] = fminf(best[c], f2 * f2 + rr);
                }
            }
            need = fmaxf(fmaxf(best[0], best[1]), fmaxf(best[2], best[3]));
        }
        float acc = 0.0f;
        #pragma unroll
        for (int c = 0; c < 4; c++)
            if (wa[c]) acc += sqrtf(best[c]);
        if (img) val1 += acc; else val0 += acc;
    }

    // block reduction of both partials
    #pragma unroll
    for (int off = 16; off > 0; off >>= 1) {
        val0 += __shfl_down_sync(0xffffffffu, val0, off);
        val1 += __shfl_down_sync(0xffffffffu, val1, off);
    }
    if (bi == 0) { warpsum0[wi] = val0; warpsum1[wi] = val1; }
    __syncthreads();
    if (wi == 0) {
        val0 = (bi < (NTHR >> 5)) ? warpsum0[bi] : 0.0f;
        val1 = (bi < (NTHR >> 5)) ? warpsum1[bi] : 0.0f;
        #pragma unroll
        for (int off = 16; off > 0; off >>= 1) {
            val0 += __shfl_down_sync(0xffffffffu, val0, off);
            val1 += __shfl_down_sync(0xffffffffu, val1, off);
        }
        if (bi == 0) {
            atomicAdd(&g_sums[0], val0);
            atomicAdd(&g_sums[1], val1);
            __threadfence();
            unsigned int tkt = atomicAdd(&g_count, 1u);
            if (tkt == (unsigned int)(NBLK - 1)) {
                float s0 = atomicAdd(&g_sums[0], 0.0f);
                float s1 = atomicAdd(&g_sums[1], 0.0f);
                float invN = 1.0f / (float)NPIX;
                float loss = (s0 * invN + s1 * invN) * 0.5f;
                out[0] = 1.0f / (1.0f + expf(-loss));
                // reset all replay state (safe: every block has passed the
                // barrier and taken its ticket before this point)
                g_sums[0] = 0.0f;
                g_sums[1] = 0.0f;
                g_count = 0u;
                g_bar = 0u;
            }
        }
    }
}

extern "C" void kernel_launch(void* const* d_in, const int* in_sizes, int n_in,
                              void* d_out, int out_size) {
    const float* preds   = (const float*)d_in[0];
    const float* targets = (const float*)d_in[1];
    float* out = (float*)d_out;
    boundary_loss_kernel<<<NBLK, NTHR>>>(preds, targets, out);
}